// round 16
// baseline (speedup 1.0000x reference)
#include <cuda_runtime.h>
#include <cuda_fp16.h>
#include <cstdint>

// Problem sizes (fixed by the reference)
#define M_ROWS 8192
#define IN_F   512
#define OUT_F  512
#define KDIM   (IN_F * 8)   // 4096

// ---------------------------------------------------------------------------
// Device scratch (allocation-free rule: __device__ globals)
// ---------------------------------------------------------------------------
__device__ __align__(16) __half g_Ah[(size_t)M_ROWS * KDIM]; // 64 MB bases (L2-resident)
__device__ __align__(16) __half g_Wh[(size_t)OUT_F * KDIM];  //  4 MB packed coeffs

// ---------------------------------------------------------------------------
// Kernel 1: pack W[o][i*8+k] = C[i][o][k], fp16.
// ---------------------------------------------------------------------------
__global__ void wpack_kernel(const float* __restrict__ coef) {
    int t = blockIdx.x * blockDim.x + threadIdx.x;
    if (t >= IN_F * OUT_F) return;
    int i = t & (IN_F - 1);
    int o = t >> 9;

    const float4* src = reinterpret_cast<const float4*>(coef + ((size_t)i * OUT_F + o) * 8);
    float4 c0 = __ldg(src);
    float4 c1 = __ldg(src + 1);

    __half2 h0 = __floats2half2_rn(c0.x, c0.y);
    __half2 h1 = __floats2half2_rn(c0.z, c0.w);
    __half2 h2 = __floats2half2_rn(c1.x, c1.y);
    __half2 h3 = __floats2half2_rn(c1.z, c1.w);
    *reinterpret_cast<uint4*>(g_Wh + (size_t)o * KDIM + i * 8) =
        make_uint4(*(uint32_t*)&h0, *(uint32_t*)&h1, *(uint32_t*)&h2, *(uint32_t*)&h3);
}

// ---------------------------------------------------------------------------
// Basis evaluation: uniform cubic B-spline, funnel-shift placement (8 halves).
// ---------------------------------------------------------------------------
__device__ __forceinline__ uint4 basis_eval(float xv, float g0, float invh) {
    float e  = __expf(2.0f * xv);
    float xn = 1.0f - 2.0f / (e + 1.0f);   // tanh(xv)

    float t  = (xn - g0) * invh;
    int   m  = (int)floorf(t);
    m = min(max(m, 3), 7);
    float u  = t - (float)m;

    float um = 1.0f - u;
    float u2 = u * u, u3 = u2 * u;
    const float s = 1.0f / 6.0f;
    float w0 = um * um * um * s;
    float w1 = (3.0f * u3 - 6.0f * u2 + 4.0f) * s;
    float w2 = (-3.0f * u3 + 3.0f * u2 + 3.0f * u + 1.0f) * s;
    float w3 = u3 * s;
    int j0 = m - 3;                        // in [0,4]

    __half2 hA = __floats2half2_rn(w0, w1);
    __half2 hB = __floats2half2_rn(w2, w3);
    uint32_t u0 = *(uint32_t*)&hA;
    uint32_t u1 = *(uint32_t*)&hB;

    uint32_t b  = (j0 & 1) << 4;
    uint32_t t0 = u0 << b;
    uint32_t t1 = __funnelshift_l(u0, u1, b);
    uint32_t t2 = __funnelshift_l(u1, 0u, b);
    int ws = j0 >> 1;

    uint4 o;
    o.x = (ws == 0) ? t0 : 0u;
    o.y = (ws == 0) ? t1 : ((ws == 1) ? t0 : 0u);
    o.z = (ws == 0) ? t2 : ((ws == 1) ? t1 : t0);
    o.w = (ws == 1) ? t2 : ((ws == 2) ? t1 : 0u);
    return o;
}

// ---------------------------------------------------------------------------
// Kernel 2: GEMM with BULK-PROLOGUE basis generation.
// CTA tile 112x256, grid (2,74) = 148 CTAs = one wave; each CTA generates its
// own 112-row A stripe (all K) into g_Ah upfront (2x redundancy across the 2
// N-CTAs; duplicate writes are bit-identical). Then the proven R13 MMA core:
// 512 threads (16 warps, 1x16), warp tile 112x16, BK=64, 3-stage cp.async,
// single barrier per chunk.
// ---------------------------------------------------------------------------
#define BM 112
#define BN 256
#define BK 64                         // halves per K chunk
#define ROWH 72                       // padded row stride (144B): LDSM conflict-free
#define STAGES 3
#define KT (KDIM / BK)                // 64
#define A_ST (BM * ROWH)              //  8064 halves
#define B_ST (BN * ROWH)              // 18432 halves
#define SMEM_BYTES (STAGES * (A_ST + B_ST) * 2)   // 158976
#define NTHREADS 512

__device__ __forceinline__ void cp16(void* smem, const void* gmem) {
    uint32_t sa = (uint32_t)__cvta_generic_to_shared(smem);
    asm volatile("cp.async.cg.shared.global [%0], [%1], 16;\n" :: "r"(sa), "l"(gmem));
}

__device__ __forceinline__ void ldsm_x4(uint32_t (&r)[4], uint32_t saddr) {
    asm volatile("ldmatrix.sync.aligned.m8n8.x4.shared.b16 {%0,%1,%2,%3}, [%4];"
                 : "=r"(r[0]), "=r"(r[1]), "=r"(r[2]), "=r"(r[3]) : "r"(saddr));
}

__device__ __forceinline__ void mma_f16(float (&d)[4], uint32_t a0, uint32_t a1,
                                        uint32_t a2, uint32_t a3,
                                        uint32_t b0, uint32_t b1) {
    asm volatile(
        "mma.sync.aligned.m16n8k16.row.col.f32.f16.f16.f32 "
        "{%0,%1,%2,%3}, {%4,%5,%6,%7}, {%8,%9}, {%0,%1,%2,%3};"
        : "+f"(d[0]), "+f"(d[1]), "+f"(d[2]), "+f"(d[3])
        : "r"(a0), "r"(a1), "r"(a2), "r"(a3), "r"(b0), "r"(b1));
}

__global__ void __launch_bounds__(NTHREADS, 1) gemm_kernel(float* __restrict__ C,
                                                           const float* __restrict__ x,
                                                           const float* __restrict__ grid) {
    extern __shared__ __half sm[];
    __half* AsBase = sm;
    __half* BsBase = sm + STAGES * A_ST;
    const uint32_t smem0 = (uint32_t)__cvta_generic_to_shared(sm);
    const uint32_t Bs0   = smem0 + STAGES * A_ST * 2;

    const int tid  = threadIdx.x;
    const int bm   = blockIdx.y * BM;
    const int bn   = blockIdx.x * BN;
    const int wid  = tid >> 5;
    const int lane = tid & 31;
    const int wn   = wid * 16;           // 0..240 (warp tile 112x16, wm = 0)
    const int gID  = lane >> 2;
    const int tg   = lane & 3;
    const int lrow = lane & 15;
    const int lcol = (lane >> 4) << 3;

    const float g0   = __ldg(grid);
    const float invh = 1.0f / (__ldg(grid + 1) - g0);

    // ---- bulk prologue: generate this CTA's 112-row A stripe (all K) ----
    // thread tid handles feature f = tid for every row; coalesced LDG + STG.128
#pragma unroll 4
    for (int i = 0; i < BM; ++i) {
        int gr = min(bm + i, M_ROWS - 1);
        float xv = __ldg(x + (size_t)gr * IN_F + tid);
        uint4 o = basis_eval(xv, g0, invh);
        *reinterpret_cast<uint4*>(g_Ah + (size_t)gr * KDIM + tid * 8) = o;
    }
    __syncthreads();   // own stripe visible to own cp.async reads below

    float acc[7][2][4];
#pragma unroll
    for (int a = 0; a < 7; ++a)
#pragma unroll
        for (int b = 0; b < 2; ++b)
#pragma unroll
            for (int c = 0; c < 4; ++c) acc[a][b][c] = 0.0f;

    auto issue = [&](int s, int kt) {
        int k0 = kt * BK;
        __half* As = AsBase + s * A_ST;
        __half* Bs = BsBase + s * B_ST;
        // A: 112 rows x 8 chunks = 896 cp16
#pragma unroll
        for (int i = 0; i < 2; ++i) {
            int id = tid + NTHREADS * i;
            if (id < BM * 8) {
                int r = id >> 3, c = id & 7;
                int gr = min(bm + r, M_ROWS - 1);
                cp16(As + r * ROWH + c * 8, g_Ah + (size_t)gr * KDIM + k0 + c * 8);
            }
        }
        // B: 256 rows x 8 chunks = 2048 cp16
#pragma unroll
        for (int i = 0; i < 4; ++i) {
            int id = tid + NTHREADS * i;
            int r = id >> 3, c = id & 7;
            cp16(Bs + r * ROWH + c * 8, g_Wh + (size_t)(bn + r) * KDIM + k0 + c * 8);
        }
        asm volatile("cp.async.commit_group;\n");
    };

    issue(0, 0);
    issue(1, 1);

    for (int kt = 0; kt < KT; ++kt) {
        if (kt < KT - 1) {
            asm volatile("cp.async.wait_group 1;\n");
        } else {
            asm volatile("cp.async.wait_group 0;\n");
        }
        __syncthreads();   // single barrier per chunk

        if (kt + 2 < KT) issue((kt + 2) % STAGES, kt + 2);

        const int s = kt % STAGES;
        const uint32_t As_u = smem0 + (s * A_ST) * 2;
        const uint32_t Bs_u = Bs0 + (s * B_ST) * 2;

#pragma unroll
        for (int ks = 0; ks < BK; ks += 16) {
            uint32_t af[7][4];
#pragma unroll
            for (int mt = 0; mt < 7; ++mt)
                ldsm_x4(af[mt], As_u + ((mt * 16 + lrow) * ROWH + ks + lcol) * 2);
            uint32_t bf[2][2];
            {
                uint32_t r[4];
                ldsm_x4(r, Bs_u + ((wn + lrow) * ROWH + ks + lcol) * 2);
                bf[0][0] = r[0]; bf[1][0] = r[1];
                bf[0][1] = r[2]; bf[1][1] = r[3];
            }
#pragma unroll
            for (int mt = 0; mt < 7; ++mt)
#pragma unroll
                for (int nt = 0; nt < 2; ++nt)
                    mma_f16(acc[mt][nt], af[mt][0], af[mt][1], af[mt][2], af[mt][3],
                            bf[nt][0], bf[nt][1]);
        }
        // no trailing barrier: next iteration's top barrier orders stage reuse
    }

    // Epilogue: guarded fp32 stores (padded M rows skipped).
#pragma unroll
    for (int mt = 0; mt < 7; ++mt) {
        int r0 = bm + mt * 16 + gID;
#pragma unroll
        for (int nt = 0; nt < 2; ++nt) {
            int c = bn + wn + nt * 8 + tg * 2;
            if (r0 < M_ROWS)
                *reinterpret_cast<float2*>(C + (size_t)r0 * OUT_F + c) =
                    make_float2(acc[mt][nt][0], acc[mt][nt][1]);
            if (r0 + 8 < M_ROWS)
                *reinterpret_cast<float2*>(C + (size_t)(r0 + 8) * OUT_F + c) =
                    make_float2(acc[mt][nt][2], acc[mt][nt][3]);
        }
    }
}

// ---------------------------------------------------------------------------
extern "C" void kernel_launch(void* const* d_in, const int* in_sizes, int n_in,
                              void* d_out, int out_size) {
    const float* x    = (const float*)d_in[0];
    const float* coef = (const float*)d_in[1];
    const float* grid = (const float*)d_in[2];
    float* out = (float*)d_out;

    wpack_kernel<<<(IN_F * OUT_F + 255) / 256, 256>>>(coef);

    static int smem_set = 0;
    if (!smem_set) {
        cudaFuncSetAttribute(gemm_kernel, cudaFuncAttributeMaxDynamicSharedMemorySize,
                             SMEM_BYTES);
        smem_set = 1;
    }
    dim3 g(OUT_F / BN, 74);   // 2 x 74 = 148 CTAs = one full wave
    gemm_kernel<<<g, NTHREADS, SMEM_BYTES>>>(out, x, grid);
}

// round 17
// speedup vs baseline: 1.4079x; 1.4079x over previous
#include <cuda_runtime.h>
#include <cuda_fp16.h>
#include <cstdint>

// Problem sizes (fixed by the reference)
#define M_ROWS 8192
#define IN_F   512
#define OUT_F  512
#define KDIM   (IN_F * 8)   // 4096

// ---------------------------------------------------------------------------
// Device scratch (allocation-free rule: __device__ globals)
// ---------------------------------------------------------------------------
__device__ __align__(16) __half g_Ah[(size_t)M_ROWS * KDIM]; // 64 MB bases (fp16)
__device__ __align__(16) __half g_Wh[(size_t)OUT_F * KDIM];  //  4 MB packed coeffs

// ---------------------------------------------------------------------------
// Kernel 1: merged prep. wpack blocks FIRST (hide under basis blocks), then
// basis blocks (1 elem/thread, best measured variant; lean-math version).
// ---------------------------------------------------------------------------
#define NB_BASIS ((M_ROWS * IN_F) / 256)          // 16384
#define NB_WPACK ((IN_F * OUT_F) / 256)           // 1024

__global__ void prep_kernel(const float* __restrict__ x,
                            const float* __restrict__ coef,
                            const float* __restrict__ grid) {
    if (blockIdx.x >= NB_WPACK) {
        // ---- basis ----
        int idx = (blockIdx.x - NB_WPACK) * blockDim.x + threadIdx.x;

        float g0   = __ldg(grid);
        float invh = 1.0f / (__ldg(grid + 1) - g0);
        float toff = -g0 * invh;

        float xv = x[idx];
        float e  = __expf(2.0f * xv);
        float xn = 1.0f - 2.0f / (e + 1.0f);   // tanh(xv)

        float t  = fmaf(xn, invh, toff);
        int   m  = (int)floorf(t);
        m = min(max(m, 3), 7);
        float u  = t - (float)m;

        float um = 1.0f - u;
        float u2 = u * u, u3 = u2 * u;
        const float s = 1.0f / 6.0f;
        float w0 = um * um * um * s;
        float w1 = (3.0f * u3 - 6.0f * u2 + 4.0f) * s;
        float w3 = u3 * s;
        float w2 = 1.0f - w0 - w1 - w3;        // partition of unity
        int j0 = m - 3;                        // in [0,4]

        __half2 hA = __floats2half2_rn(w0, w1);
        __half2 hB = __floats2half2_rn(w2, w3);
        uint32_t u0 = *(uint32_t*)&hA;
        uint32_t u1 = *(uint32_t*)&hB;

        uint32_t b  = (j0 & 1) << 4;
        uint32_t t0 = u0 << b;
        uint32_t t1 = __funnelshift_l(u0, u1, b);
        uint32_t t2 = __funnelshift_l(u1, 0u, b);
        int ws = j0 >> 1;

        uint32_t o0 = (ws == 0) ? t0 : 0u;
        uint32_t o1 = (ws == 0) ? t1 : ((ws == 1) ? t0 : 0u);
        uint32_t o2 = (ws == 0) ? t2 : ((ws == 1) ? t1 : t0);
        uint32_t o3 = (ws == 1) ? t2 : ((ws == 2) ? t1 : 0u);

        *reinterpret_cast<uint4*>(g_Ah + (size_t)idx * 8) = make_uint4(o0, o1, o2, o3);
    } else {
        // ---- wpack:  W[o][i*8+k] = C[i][o][k], fp16 ----
        int t = blockIdx.x * blockDim.x + threadIdx.x;
        int i = t & (IN_F - 1);
        int o = t >> 9;

        const float4* src = reinterpret_cast<const float4*>(coef + ((size_t)i * OUT_F + o) * 8);
        float4 c0 = __ldg(src);
        float4 c1 = __ldg(src + 1);

        __half2 h0 = __floats2half2_rn(c0.x, c0.y);
        __half2 h1 = __floats2half2_rn(c0.z, c0.w);
        __half2 h2 = __floats2half2_rn(c1.x, c1.y);
        __half2 h3 = __floats2half2_rn(c1.z, c1.w);
        *reinterpret_cast<uint4*>(g_Wh + (size_t)o * KDIM + i * 8) =
            make_uint4(*(uint32_t*)&h0, *(uint32_t*)&h1, *(uint32_t*)&h2, *(uint32_t*)&h3);
    }
}

// ---------------------------------------------------------------------------
// Kernel 2: GEMM, mma.sync m16n8k16 fp16->fp32, ldmatrix.  (R13 verbatim)
// CTA tile 224x128, grid (4,37) = 148 CTAs = one wave. 512 threads, 16 warps
// (2x8), warp tile 112x16. BK=64, 3-stage cp.async, single barrier per chunk.
// ---------------------------------------------------------------------------
#define BM 224
#define BN 128
#define BK 64                         // halves per K chunk
#define ROWH 72                       // padded row stride (144B): LDSM conflict-free
#define STAGES 3
#define KT (KDIM / BK)                // 64
#define A_ST (BM * ROWH)              // 16128 halves
#define B_ST (BN * ROWH)              //  9216 halves
#define SMEM_BYTES (STAGES * (A_ST + B_ST) * 2)   // 152064
#define NTHREADS 512

__device__ __forceinline__ void cp16(void* smem, const void* gmem) {
    uint32_t sa = (uint32_t)__cvta_generic_to_shared(smem);
    asm volatile("cp.async.cg.shared.global [%0], [%1], 16;\n" :: "r"(sa), "l"(gmem));
}

__device__ __forceinline__ void ldsm_x4(uint32_t (&r)[4], uint32_t saddr) {
    asm volatile("ldmatrix.sync.aligned.m8n8.x4.shared.b16 {%0,%1,%2,%3}, [%4];"
                 : "=r"(r[0]), "=r"(r[1]), "=r"(r[2]), "=r"(r[3]) : "r"(saddr));
}

__device__ __forceinline__ void mma_f16(float (&d)[4], uint32_t a0, uint32_t a1,
                                        uint32_t a2, uint32_t a3,
                                        uint32_t b0, uint32_t b1) {
    asm volatile(
        "mma.sync.aligned.m16n8k16.row.col.f32.f16.f16.f32 "
        "{%0,%1,%2,%3}, {%4,%5,%6,%7}, {%8,%9}, {%0,%1,%2,%3};"
        : "+f"(d[0]), "+f"(d[1]), "+f"(d[2]), "+f"(d[3])
        : "r"(a0), "r"(a1), "r"(a2), "r"(a3), "r"(b0), "r"(b1));
}

__global__ void __launch_bounds__(NTHREADS, 1) gemm_kernel(float* __restrict__ C) {
    extern __shared__ __half sm[];
    __half* AsBase = sm;
    __half* BsBase = sm + STAGES * A_ST;
    const uint32_t smem0 = (uint32_t)__cvta_generic_to_shared(sm);
    const uint32_t Bs0   = smem0 + STAGES * A_ST * 2;

    const int tid  = threadIdx.x;
    const int bm   = blockIdx.y * BM;
    const int bn   = blockIdx.x * BN;
    const int wid  = tid >> 5;
    const int lane = tid & 31;
    const int wm   = (wid >> 3) * 112;   // 0 / 112
    const int wn   = (wid & 7) * 16;     // 0..112
    const int gID  = lane >> 2;
    const int tg   = lane & 3;
    const int lrow = lane & 15;
    const int lcol = (lane >> 4) << 3;

    float acc[7][2][4];
#pragma unroll
    for (int a = 0; a < 7; ++a)
#pragma unroll
        for (int b = 0; b < 2; ++b)
#pragma unroll
            for (int c = 0; c < 4; ++c) acc[a][b][c] = 0.0f;

    auto issue = [&](int s, int kt) {
        int k0 = kt * BK;
        __half* As = AsBase + s * A_ST;
        __half* Bs = BsBase + s * B_ST;
#pragma unroll
        for (int i = 0; i < 4; ++i) {            // A: 224 rows x 8 chunks = 1792
            int id = tid + NTHREADS * i;
            if (id < BM * 8) {
                int r = id >> 3, c = id & 7;
                int gr = min(bm + r, M_ROWS - 1);
                cp16(As + r * ROWH + c * 8, g_Ah + (size_t)gr * KDIM + k0 + c * 8);
            }
        }
#pragma unroll
        for (int i = 0; i < 2; ++i) {            // B: 128 rows x 8 chunks = 1024
            int id = tid + NTHREADS * i;
            int r = id >> 3, c = id & 7;
            cp16(Bs + r * ROWH + c * 8, g_Wh + (size_t)(bn + r) * KDIM + k0 + c * 8);
        }
        asm volatile("cp.async.commit_group;\n");
    };

    issue(0, 0);
    issue(1, 1);

    for (int kt = 0; kt < KT; ++kt) {
        if (kt < KT - 1) {
            asm volatile("cp.async.wait_group 1;\n");
        } else {
            asm volatile("cp.async.wait_group 0;\n");
        }
        __syncthreads();   // single barrier per chunk

        if (kt + 2 < KT) issue((kt + 2) % STAGES, kt + 2);

        const int s = kt % STAGES;
        const uint32_t As_u = smem0 + (s * A_ST) * 2;
        const uint32_t Bs_u = Bs0 + (s * B_ST) * 2;

#pragma unroll
        for (int ks = 0; ks < BK; ks += 16) {
            uint32_t af[7][4];
#pragma unroll
            for (int mt = 0; mt < 7; ++mt)
                ldsm_x4(af[mt], As_u + ((wm + mt * 16 + lrow) * ROWH + ks + lcol) * 2);
            uint32_t bf[2][2];
            {
                uint32_t r[4];
                ldsm_x4(r, Bs_u + ((wn + lrow) * ROWH + ks + lcol) * 2);
                bf[0][0] = r[0]; bf[1][0] = r[1];
                bf[0][1] = r[2]; bf[1][1] = r[3];
            }
#pragma unroll
            for (int mt = 0; mt < 7; ++mt)
#pragma unroll
                for (int nt = 0; nt < 2; ++nt)
                    mma_f16(acc[mt][nt], af[mt][0], af[mt][1], af[mt][2], af[mt][3],
                            bf[nt][0], bf[nt][1]);
        }
        // no trailing barrier: next iteration's top barrier orders stage reuse
    }

    // Epilogue: guarded fp32 stores (padded M rows skipped).
#pragma unroll
    for (int mt = 0; mt < 7; ++mt) {
        int r0 = bm + wm + mt * 16 + gID;
#pragma unroll
        for (int nt = 0; nt < 2; ++nt) {
            int c = bn + wn + nt * 8 + tg * 2;
            if (r0 < M_ROWS)
                *reinterpret_cast<float2*>(C + (size_t)r0 * OUT_F + c) =
                    make_float2(acc[mt][nt][0], acc[mt][nt][1]);
            if (r0 + 8 < M_ROWS)
                *reinterpret_cast<float2*>(C + (size_t)(r0 + 8) * OUT_F + c) =
                    make_float2(acc[mt][nt][2], acc[mt][nt][3]);
        }
    }
}

// ---------------------------------------------------------------------------
extern "C" void kernel_launch(void* const* d_in, const int* in_sizes, int n_in,
                              void* d_out, int out_size) {
    const float* x    = (const float*)d_in[0];
    const float* coef = (const float*)d_in[1];
    const float* grid = (const float*)d_in[2];
    float* out = (float*)d_out;

    prep_kernel<<<NB_BASIS + NB_WPACK, 256>>>(x, coef, grid);

    static int smem_set = 0;
    if (!smem_set) {
        cudaFuncSetAttribute(gemm_kernel, cudaFuncAttributeMaxDynamicSharedMemorySize,
                             SMEM_BYTES);
        smem_set = 1;
    }
    dim3 g(OUT_F / BN, 37);   // 4 x 37 = 148 CTAs = one full wave
    gemm_kernel<<<g, NTHREADS, SMEM_BYTES>>>(out);
}